// round 14
// baseline (speedup 1.0000x reference)
#include <cuda_runtime.h>
#include <cuda_fp16.h>
#include <math.h>

#define CH   128
#define HH   64
#define WW   128
#define DD   32
#define NV   2

#define TWO_PI_F 6.2831853071795864769f
#define PI_F     3.1415926535897932385f

// channel-last fp16 features: featH[v][h][w][c] (+ pad)
__device__ __half g_featH[NV * HH * WW * CH + 2 * CH];     // 4 MB + pad
__device__ float  g_pose[2][12];
__device__ float  g_depth[2][DD];

// ---------------------------------------------------------------------------
// Transpose (v,c,h,w) -> (v,h,w,c) fp16, coalesced half2 stores.
// Block (0,0,0) also computes pose/depth tables.
// grid: (W/32, C/32, V*H), block (32, 8)
// ---------------------------------------------------------------------------
__global__ void transpose_kernel(const float* __restrict__ feat,
                                 const float* __restrict__ ex,
                                 const float* __restrict__ nearp,
                                 const float* __restrict__ farp) {
    __shared__ float tile[32][33];
    int v  = blockIdx.z >> 6;
    int h  = blockIdx.z & 63;
    int w0 = blockIdx.x << 5;
    int c0 = blockIdx.y << 5;
    int tx = threadIdx.x, ty = threadIdx.y;
    int lt = ty * 32 + tx;

    if (blockIdx.x == 0 && blockIdx.y == 0 && blockIdx.z == 0) {
        if (lt == 0) {
            float R0[3][3], R1[3][3], t0[3], t1[3];
            #pragma unroll
            for (int i = 0; i < 3; ++i) {
                #pragma unroll
                for (int j = 0; j < 3; ++j) {
                    R0[i][j] = ex[i * 4 + j];
                    R1[i][j] = ex[16 + i * 4 + j];
                }
                t0[i] = ex[i * 4 + 3];
                t1[i] = ex[16 + i * 4 + 3];
            }
            float Rp[3][3], tp[3];
            #pragma unroll
            for (int i = 0; i < 3; ++i) {
                #pragma unroll
                for (int j = 0; j < 3; ++j)
                    Rp[i][j] = R1[0][i] * R0[0][j] + R1[1][i] * R0[1][j] + R1[2][i] * R0[2][j];
                tp[i] = R1[0][i] * (t0[0] - t1[0]) + R1[1][i] * (t0[1] - t1[1])
                      + R1[2][i] * (t0[2] - t1[2]);
            }
            #pragma unroll
            for (int i = 0; i < 3; ++i) {
                #pragma unroll
                for (int j = 0; j < 3; ++j) {
                    g_pose[0][i * 4 + j] = Rp[i][j];
                    g_pose[1][i * 4 + j] = Rp[j][i];
                }
                g_pose[0][i * 4 + 3] = tp[i];
                g_pose[1][i * 4 + 3] = -(Rp[0][i] * tp[0] + Rp[1][i] * tp[1] + Rp[2][i] * tp[2]);
            }
        }
        if (lt >= 64 && lt < 64 + 2 * DD) {
            int t = lt - 64;
            int n = t >> 5;
            int d = t & (DD - 1);
            float mind = 1.0f / farp[n];
            float maxd = 1.0f / nearp[n];
            float lin  = (float)d * (1.0f / (float)(DD - 1));
            g_depth[n][d] = 1.0f / (mind + lin * (maxd - mind));
        }
    }

    #pragma unroll
    for (int i = 0; i < 32; i += 8)
        tile[ty + i][tx] = feat[(((v * CH) + (c0 + ty + i)) * HH + h) * WW + (w0 + tx)];
    __syncthreads();

    // coalesced half2 stores: 16 threads cover 32 channels for one w
    int cp = tx & 15;
    #pragma unroll
    for (int i = 0; i < 32; i += 16) {
        int wloc = ty + 8 * (tx >> 4) + i;        // 0..31
        __half2 hv = __floats2half2_rn(tile[2 * cp][wloc], tile[2 * cp + 1][wloc]);
        *reinterpret_cast<__half2*>(
            g_featH + (size_t)(((v * HH + h) * WW) + (w0 + wloc)) * CH + c0 + 2 * cp) = hv;
    }
}

__device__ __forceinline__ __half2 u2h2(unsigned int u) {
    return *reinterpret_cast<__half2*>(&u);
}

// ---------------------------------------------------------------------------
// Main: block = (n, h, 32 adjacent w), 1024 threads, 2 blocks/SM (grid 512
// -> 1.73 waves instead of 2.31). Warp = 2 pixels (16 lanes, 8 ch/lane) x 16
// depths — same inner loop as the best (R11) kernel.
// Phase 1: thread (px=tid&31, d=tid>>5) projects -> {lin0|lin1, fp16 weights}.
// Phase 2: per depth: LDS.128 broadcast; 4 x LDG.128; half2 bilinear + dot;
//          shfl(8)+shfl(4); 4 partials to smem.
// Phase 3: thread (d=tid>>5, px=tid&31): 1 LDS.128 + 3 FADD, coalesced STG.
// ---------------------------------------------------------------------------
__global__ void __launch_bounds__(1024, 2) corr_kernel(float* __restrict__ out) {
    int bid = blockIdx.x;                 // 512 blocks
    int wt = bid & 3;                     // 4 tiles of 32 pixels
    int h  = (bid >> 2) & (HH - 1);
    int n  = bid >> 8;

    __shared__ float s_pose[12];
    __shared__ float s_depth[DD];
    __shared__ float s_projF[32 * 132];               // per px: 32 x float4 + pad
    __shared__ __align__(16) float s_part[DD][32][4]; // 4 partials, conflict-free

    int tid  = threadIdx.x;
    int lane = tid & 31;
    int wid  = tid >> 5;

    if (tid < 12) s_pose[tid] = g_pose[n][tid];
    if (tid >= 32 && tid < 64) s_depth[tid - 32] = g_depth[n][tid - 32];
    __syncthreads();

    // ---- phase 1: one thread per (pixel, depth) ----
    {
        int px = tid & 31;
        int d  = tid >> 5;
        int w  = wt * 32 + px;

        float theta = ((float)w + 0.5f) * (TWO_PI_F / (float)WW);
        float phi   = ((float)h + 0.5f) * (PI_F / (float)HH);
        float sth, cth, sphi, cphi;
        sincosf(theta, &sth, &cth);
        sincosf(phi, &sphi, &cphi);
        float dep = s_depth[d];
        float px3 = dep * sphi * sth;
        float py3 = dep * cphi;
        float pz3 = dep * sphi * cth;

        float X = s_pose[0] * px3 + s_pose[1] * py3 + s_pose[2]  * pz3 + s_pose[3];
        float Y = s_pose[4] * px3 + s_pose[5] * py3 + s_pose[6]  * pz3 + s_pose[7];
        float Z = s_pose[8] * px3 + s_pose[9] * py3 + s_pose[10] * pz3 + s_pose[11];

        float r = fmaxf(sqrtf(X * X + Y * Y + Z * Z), 0.001f);
        float cph = fminf(fmaxf(Y / r, -1.0f), 1.0f);
        float phw = acosf(cph);
        float thw = atan2f(X, Z);
        if (thw < 0.0f) thw += TWO_PI_F;

        float ix = thw * ((float)(WW - 1) / TWO_PI_F);   // [0, 127)
        float iy = phw * ((float)(HH - 1) / PI_F);       // [0, 63]

        float x0f = floorf(ix), y0f = floorf(iy);
        float wx1 = ix - x0f, wy1 = iy - y0f;
        float wx0 = 1.0f - wx1, wy0 = 1.0f - wy1;

        int x0 = min((int)x0f, WW - 2);
        int y0 = (int)y0f;
        int y1 = min(y0 + 1, HH - 1);

        int lin0 = (y0 << 7) + x0;
        int lin1 = (y1 << 7) + x0;
        int packed = lin0 | (lin1 << 13);

        __half2 wA = __floats2half2_rn(wx0 * wy0, wx1 * wy0);   // (w00, w10)
        __half2 wB = __floats2half2_rn(wx0 * wy1, wx1 * wy1);   // (w01, w11)

        *reinterpret_cast<float4*>(&s_projF[px * 132 + d * 4]) = make_float4(
            __int_as_float(packed),
            __uint_as_float(*reinterpret_cast<unsigned int*>(&wA)),
            __uint_as_float(*reinterpret_cast<unsigned int*>(&wB)),
            0.0f);
    }
    __syncthreads();

    // ---- phase 2: 2 pixels per warp, 16 depths per warp ----
    int pxl = ((wid & 15) << 1) + (lane >> 4);   // this lane's pixel (0..31)
    int dlo = (wid >> 4) << 4;                   // depth range base {0,16}
    int cl  = lane & 15;                         // channel-group within pixel
    int w   = wt * 32 + pxl;

    const uint4* __restrict__ f0p = reinterpret_cast<const uint4*>(
        g_featH + (size_t)(((n * HH + h) * WW) + w) * CH) + cl;
    uint4 f0q = *f0p;
    __half2 f00 = u2h2(f0q.x), f01 = u2h2(f0q.y), f02 = u2h2(f0q.z), f03 = u2h2(f0q.w);

    const __half* __restrict__ hb = g_featH + (size_t)(1 - n) * HH * WW * CH;

    #pragma unroll 4
    for (int it = 0; it < 16; ++it) {
        int d = dlo + it;
        float4 pw = *reinterpret_cast<const float4*>(&s_projF[pxl * 132 + d * 4]);
        int pk = __float_as_int(pw.x);
        int lin0 = pk & 8191;
        int lin1 = (pk >> 13) & 8191;

        __half2 pA = u2h2(__float_as_uint(pw.y));   // (w00, w10)
        __half2 pB = u2h2(__float_as_uint(pw.z));   // (w01, w11)

        const uint4* r0 = reinterpret_cast<const uint4*>(hb + (lin0 << 7)) + cl;
        const uint4* r1 = reinterpret_cast<const uint4*>(hb + (lin1 << 7)) + cl;
        uint4 q00 = r0[0];
        uint4 q10 = r0[16];    // column x0+1: +256B immediate
        uint4 q01 = r1[0];
        uint4 q11 = r1[16];

        // bilinear combine in half2
        __half2 c0 = __hmul2(__low2half2(pA), u2h2(q00.x));
        c0 = __hfma2(__high2half2(pA), u2h2(q10.x), c0);
        c0 = __hfma2(__low2half2(pB),  u2h2(q01.x), c0);
        c0 = __hfma2(__high2half2(pB), u2h2(q11.x), c0);

        __half2 c1 = __hmul2(__low2half2(pA), u2h2(q00.y));
        c1 = __hfma2(__high2half2(pA), u2h2(q10.y), c1);
        c1 = __hfma2(__low2half2(pB),  u2h2(q01.y), c1);
        c1 = __hfma2(__high2half2(pB), u2h2(q11.y), c1);

        __half2 c2 = __hmul2(__low2half2(pA), u2h2(q00.z));
        c2 = __hfma2(__high2half2(pA), u2h2(q10.z), c2);
        c2 = __hfma2(__low2half2(pB),  u2h2(q01.z), c2);
        c2 = __hfma2(__high2half2(pB), u2h2(q11.z), c2);

        __half2 c3 = __hmul2(__low2half2(pA), u2h2(q00.w));
        c3 = __hfma2(__high2half2(pA), u2h2(q10.w), c3);
        c3 = __hfma2(__low2half2(pB),  u2h2(q01.w), c3);
        c3 = __hfma2(__high2half2(pB), u2h2(q11.w), c3);

        // dot with own-view features
        __half2 ah = __hmul2(f00, c0);
        ah = __hfma2(f01, c1, ah);
        ah = __hfma2(f02, c2, ah);
        ah = __hfma2(f03, c3, ah);

        float2 e = __half22float2(ah);
        float acc = e.x + e.y;

        acc += __shfl_xor_sync(0xffffffffu, acc, 8);
        acc += __shfl_xor_sync(0xffffffffu, acc, 4);
        if ((lane & 15) < 4) s_part[d][pxl][lane & 3] = acc;
    }
    __syncthreads();

    // ---- phase 3: thread (d, px): 1 x LDS.128 + 3 FADD; coalesced store ----
    {
        int d  = tid >> 5;
        int px = tid & 31;
        float4 a = *reinterpret_cast<const float4*>(s_part[d][px]);
        float sum = (a.x + a.y) + (a.z + a.w);
        out[(((n * DD + d) * HH + h) << 7) + wt * 32 + px] =
            sum * 0.08838834764831844f;   // 1/sqrt(128)
    }
}

extern "C" void kernel_launch(void* const* d_in, const int* in_sizes, int n_in,
                              void* d_out, int out_size) {
    const float* features = (const float*)d_in[0];
    const float* extr     = (const float*)d_in[1];
    const float* nearp    = (const float*)d_in[2];
    const float* farp     = (const float*)d_in[3];
    float* out = (float*)d_out;

    transpose_kernel<<<dim3(WW / 32, CH / 32, NV * HH), dim3(32, 8)>>>(
        features, extr, nearp, farp);
    corr_kernel<<<NV * HH * (WW / 32), 1024>>>(out);
}

// round 15
// speedup vs baseline: 1.7664x; 1.7664x over previous
#include <cuda_runtime.h>
#include <cuda_fp16.h>
#include <math.h>

#define CH   128
#define HH   64
#define WW   128
#define DD   32
#define NV   2

#define TWO_PI_F 6.2831853071795864769f
#define PI_F     3.1415926535897932385f

// channel-last fp16 features: featH[v][h][w][c] (+ pad)
__device__ __half g_featH[NV * HH * WW * CH + 2 * CH];     // 4 MB + pad
__device__ float  g_pose[2][12];
__device__ float  g_depth[2][DD];

// ---------------------------------------------------------------------------
// Transpose (v,c,h,w) -> (v,h,w,c) fp16, coalesced half2 stores.
// Block (0,0,0) also computes pose/depth tables.
// grid: (W/32, C/32, V*H), block (32, 8)
// ---------------------------------------------------------------------------
__global__ void transpose_kernel(const float* __restrict__ feat,
                                 const float* __restrict__ ex,
                                 const float* __restrict__ nearp,
                                 const float* __restrict__ farp) {
    __shared__ float tile[32][33];
    int v  = blockIdx.z >> 6;
    int h  = blockIdx.z & 63;
    int w0 = blockIdx.x << 5;
    int c0 = blockIdx.y << 5;
    int tx = threadIdx.x, ty = threadIdx.y;
    int lt = ty * 32 + tx;

    if (blockIdx.x == 0 && blockIdx.y == 0 && blockIdx.z == 0) {
        if (lt == 0) {
            float R0[3][3], R1[3][3], t0[3], t1[3];
            #pragma unroll
            for (int i = 0; i < 3; ++i) {
                #pragma unroll
                for (int j = 0; j < 3; ++j) {
                    R0[i][j] = ex[i * 4 + j];
                    R1[i][j] = ex[16 + i * 4 + j];
                }
                t0[i] = ex[i * 4 + 3];
                t1[i] = ex[16 + i * 4 + 3];
            }
            float Rp[3][3], tp[3];
            #pragma unroll
            for (int i = 0; i < 3; ++i) {
                #pragma unroll
                for (int j = 0; j < 3; ++j)
                    Rp[i][j] = R1[0][i] * R0[0][j] + R1[1][i] * R0[1][j] + R1[2][i] * R0[2][j];
                tp[i] = R1[0][i] * (t0[0] - t1[0]) + R1[1][i] * (t0[1] - t1[1])
                      + R1[2][i] * (t0[2] - t1[2]);
            }
            #pragma unroll
            for (int i = 0; i < 3; ++i) {
                #pragma unroll
                for (int j = 0; j < 3; ++j) {
                    g_pose[0][i * 4 + j] = Rp[i][j];
                    g_pose[1][i * 4 + j] = Rp[j][i];
                }
                g_pose[0][i * 4 + 3] = tp[i];
                g_pose[1][i * 4 + 3] = -(Rp[0][i] * tp[0] + Rp[1][i] * tp[1] + Rp[2][i] * tp[2]);
            }
        }
        if (lt >= 64 && lt < 64 + 2 * DD) {
            int t = lt - 64;
            int n = t >> 5;
            int d = t & (DD - 1);
            float mind = 1.0f / farp[n];
            float maxd = 1.0f / nearp[n];
            float lin  = (float)d * (1.0f / (float)(DD - 1));
            g_depth[n][d] = 1.0f / (mind + lin * (maxd - mind));
        }
    }

    #pragma unroll
    for (int i = 0; i < 32; i += 8)
        tile[ty + i][tx] = feat[(((v * CH) + (c0 + ty + i)) * HH + h) * WW + (w0 + tx)];
    __syncthreads();

    // coalesced half2 stores: 16 threads cover 32 channels for one w
    int cp = tx & 15;
    #pragma unroll
    for (int i = 0; i < 32; i += 16) {
        int wloc = ty + 8 * (tx >> 4) + i;        // 0..31
        __half2 hv = __floats2half2_rn(tile[2 * cp][wloc], tile[2 * cp + 1][wloc]);
        *reinterpret_cast<__half2*>(
            g_featH + (size_t)(((v * HH + h) * WW) + (w0 + wloc)) * CH + c0 + 2 * cp) = hv;
    }
}

__device__ __forceinline__ __half2 u2h2(unsigned int u) {
    return *reinterpret_cast<__half2*>(&u);
}

// ---------------------------------------------------------------------------
// Main: block = (n, h, 8 adjacent w), 256 threads, 6 blocks/SM (grid 2048 —
// quarter-size blocks cut wave-tail quantization). Warp = 2 pixels (16 lanes,
// 8 ch/lane) x 16 depths — identical hot loop to the best (R11) kernel.
// Phase 1: thread (px=tid&7, d=tid>>3) projects -> {lin0|lin1, fp16 weights}.
// Phase 2: per depth: LDS.128 broadcast; 4 x LDG.128; half2 bilinear + dot;
//          1 shfl(8); 8 partials to smem.
// Phase 3: thread (d=tid>>3, px=tid&7): 2 x LDS.128 + 7 FADD, coalesced STG.
// ---------------------------------------------------------------------------
__global__ void __launch_bounds__(256, 6) corr_kernel(float* __restrict__ out) {
    int bid = blockIdx.x;                 // 2048 blocks
    int wt = bid & 15;                    // 16 tiles of 8 pixels
    int h  = (bid >> 4) & (HH - 1);
    int n  = bid >> 10;

    __shared__ float s_pose[12];
    __shared__ float s_depth[DD];
    __shared__ float s_projF[8 * 132];                 // per px: 32 x float4 + pad
    __shared__ __align__(16) float s_part[DD][8][12];  // 8 partials + align pad

    int tid  = threadIdx.x;
    int lane = tid & 31;
    int wid  = tid >> 5;

    if (tid < 12) s_pose[tid] = g_pose[n][tid];
    if (tid >= 32 && tid < 64) s_depth[tid - 32] = g_depth[n][tid - 32];
    __syncthreads();

    // ---- phase 1: one thread per (pixel, depth) ----
    {
        int px = tid & 7;
        int d  = tid >> 3;
        int w  = wt * 8 + px;

        float theta = ((float)w + 0.5f) * (TWO_PI_F / (float)WW);
        float phi   = ((float)h + 0.5f) * (PI_F / (float)HH);
        float sth, cth, sphi, cphi;
        sincosf(theta, &sth, &cth);
        sincosf(phi, &sphi, &cphi);
        float dep = s_depth[d];
        float px3 = dep * sphi * sth;
        float py3 = dep * cphi;
        float pz3 = dep * sphi * cth;

        float X = s_pose[0] * px3 + s_pose[1] * py3 + s_pose[2]  * pz3 + s_pose[3];
        float Y = s_pose[4] * px3 + s_pose[5] * py3 + s_pose[6]  * pz3 + s_pose[7];
        float Z = s_pose[8] * px3 + s_pose[9] * py3 + s_pose[10] * pz3 + s_pose[11];

        float r = fmaxf(sqrtf(X * X + Y * Y + Z * Z), 0.001f);
        float cph = fminf(fmaxf(Y / r, -1.0f), 1.0f);
        float phw = acosf(cph);
        float thw = atan2f(X, Z);
        if (thw < 0.0f) thw += TWO_PI_F;

        float ix = thw * ((float)(WW - 1) / TWO_PI_F);   // [0, 127)
        float iy = phw * ((float)(HH - 1) / PI_F);       // [0, 63]

        float x0f = floorf(ix), y0f = floorf(iy);
        float wx1 = ix - x0f, wy1 = iy - y0f;
        float wx0 = 1.0f - wx1, wy0 = 1.0f - wy1;

        int x0 = min((int)x0f, WW - 2);
        int y0 = (int)y0f;
        int y1 = min(y0 + 1, HH - 1);

        int lin0 = (y0 << 7) + x0;
        int lin1 = (y1 << 7) + x0;
        int packed = lin0 | (lin1 << 13);

        __half2 wA = __floats2half2_rn(wx0 * wy0, wx1 * wy0);   // (w00, w10)
        __half2 wB = __floats2half2_rn(wx0 * wy1, wx1 * wy1);   // (w01, w11)

        *reinterpret_cast<float4*>(&s_projF[px * 132 + d * 4]) = make_float4(
            __int_as_float(packed),
            __uint_as_float(*reinterpret_cast<unsigned int*>(&wA)),
            __uint_as_float(*reinterpret_cast<unsigned int*>(&wB)),
            0.0f);
    }
    __syncthreads();

    // ---- phase 2: 2 pixels per warp, 16 depths per warp ----
    int pxl = ((wid & 3) << 1) + (lane >> 4);    // this lane's pixel (0..7)
    int dlo = (wid >> 2) << 4;                   // depth range base {0,16}
    int cl  = lane & 15;                         // channel-group within pixel
    int w   = wt * 8 + pxl;

    const uint4* __restrict__ f0p = reinterpret_cast<const uint4*>(
        g_featH + (size_t)(((n * HH + h) * WW) + w) * CH) + cl;
    uint4 f0q = *f0p;
    __half2 f00 = u2h2(f0q.x), f01 = u2h2(f0q.y), f02 = u2h2(f0q.z), f03 = u2h2(f0q.w);

    const __half* __restrict__ hb = g_featH + (size_t)(1 - n) * HH * WW * CH;

    #pragma unroll 4
    for (int it = 0; it < 16; ++it) {
        int d = dlo + it;
        float4 pw = *reinterpret_cast<const float4*>(&s_projF[pxl * 132 + d * 4]);
        int pk = __float_as_int(pw.x);
        int lin0 = pk & 8191;
        int lin1 = (pk >> 13) & 8191;

        __half2 pA = u2h2(__float_as_uint(pw.y));   // (w00, w10)
        __half2 pB = u2h2(__float_as_uint(pw.z));   // (w01, w11)

        const uint4* r0 = reinterpret_cast<const uint4*>(hb + (lin0 << 7)) + cl;
        const uint4* r1 = reinterpret_cast<const uint4*>(hb + (lin1 << 7)) + cl;
        uint4 q00 = r0[0];
        uint4 q10 = r0[16];    // column x0+1: +256B immediate
        uint4 q01 = r1[0];
        uint4 q11 = r1[16];

        // bilinear combine in half2
        __half2 c0 = __hmul2(__low2half2(pA), u2h2(q00.x));
        c0 = __hfma2(__high2half2(pA), u2h2(q10.x), c0);
        c0 = __hfma2(__low2half2(pB),  u2h2(q01.x), c0);
        c0 = __hfma2(__high2half2(pB), u2h2(q11.x), c0);

        __half2 c1 = __hmul2(__low2half2(pA), u2h2(q00.y));
        c1 = __hfma2(__high2half2(pA), u2h2(q10.y), c1);
        c1 = __hfma2(__low2half2(pB),  u2h2(q01.y), c1);
        c1 = __hfma2(__high2half2(pB), u2h2(q11.y), c1);

        __half2 c2 = __hmul2(__low2half2(pA), u2h2(q00.z));
        c2 = __hfma2(__high2half2(pA), u2h2(q10.z), c2);
        c2 = __hfma2(__low2half2(pB),  u2h2(q01.z), c2);
        c2 = __hfma2(__high2half2(pB), u2h2(q11.z), c2);

        __half2 c3 = __hmul2(__low2half2(pA), u2h2(q00.w));
        c3 = __hfma2(__high2half2(pA), u2h2(q10.w), c3);
        c3 = __hfma2(__low2half2(pB),  u2h2(q01.w), c3);
        c3 = __hfma2(__high2half2(pB), u2h2(q11.w), c3);

        // dot with own-view features
        __half2 ah = __hmul2(f00, c0);
        ah = __hfma2(f01, c1, ah);
        ah = __hfma2(f02, c2, ah);
        ah = __hfma2(f03, c3, ah);

        float2 e = __half22float2(ah);
        float acc = e.x + e.y;

        acc += __shfl_xor_sync(0xffffffffu, acc, 8);
        if ((lane & 15) < 8) s_part[d][pxl][lane & 7] = acc;
    }
    __syncthreads();

    // ---- phase 3: thread (d, px): 2 x LDS.128 + 7 FADD; coalesced store ----
    {
        int d  = tid >> 3;
        int px = tid & 7;
        const float4* pp = reinterpret_cast<const float4*>(s_part[d][px]);
        float4 a = pp[0], b = pp[1];
        float sum = ((a.x + a.y) + (a.z + a.w)) + ((b.x + b.y) + (b.z + b.w));
        out[(((n * DD + d) * HH + h) << 7) + wt * 8 + px] =
            sum * 0.08838834764831844f;   // 1/sqrt(128)
    }
}

extern "C" void kernel_launch(void* const* d_in, const int* in_sizes, int n_in,
                              void* d_out, int out_size) {
    const float* features = (const float*)d_in[0];
    const float* extr     = (const float*)d_in[1];
    const float* nearp    = (const float*)d_in[2];
    const float* farp     = (const float*)d_in[3];
    float* out = (float*)d_out;

    transpose_kernel<<<dim3(WW / 32, CH / 32, NV * HH), dim3(32, 8)>>>(
        features, extr, nearp, farp);
    corr_kernel<<<NV * HH * (WW / 8), 256>>>(out);
}